// round 2
// baseline (speedup 1.0000x reference)
#include <cuda_runtime.h>
#include <math.h>

#define V      100000
#define E      1000000
#define D      200
#define R      474
#define HALF   500000
#define NPB    16        // nodes per block in main kernel
#define XST    204       // xs row stride in floats (mult of 4 -> 16B aligned quads)
#define TPB    224       // 7 warps, threads 0..199 own features
#define NBLK   98        // ceil(V/1024) for scan
#define NQ     50        // D/4 j-quads

// ---------------- device scratch (no runtime allocation allowed) ------------
__device__ float    g_Mtab[2 * R * D];      // softmax(rel @ W)/3, key = et + 474*is_out
__device__ float    g_Weff4[NQ * D * 4];    // j-quad-major: [(j/4)*200 + o]*4 + (j&3)
__device__ int      g_cnt[V];
__device__ int      g_off[V + 1];
__device__ int      g_cur[V];
__device__ uint2    g_edge[E];              // {key, float_bits(norm)}
__device__ int      g_bsum[128];
__device__ float    g_stats[4 * D];         // colsum, colsumsq, scale, shift

__device__ __forceinline__ void fma2(unsigned long long& acc,
                                     unsigned long long a,
                                     unsigned long long b) {
    asm("fma.rn.f32x2 %0, %1, %2, %0;" : "+l"(acc) : "l"(a), "l"(b));
}

// ---------------- merged precompute: mtab + weff + zero ----------------------
// blocks [0,948): message table; [948,1148): Weff; [1148,1246): zero cnt/stats
__global__ void k_pre(const float* __restrict__ rel,
                      const float* __restrict__ in_w,
                      const float* __restrict__ out_w,
                      const float* __restrict__ loop_rel,
                      const float* __restrict__ loop_w) {
    int b = blockIdx.x, t = threadIdx.x;
    if (b < 2 * R) {
        // softmax(rel_repr[r] @ W) / 3
        __shared__ float rr[D];
        __shared__ float red[256];
        int s = b / R, r = b % R;
        const float* W = s ? out_w : in_w;
        for (int i = t; i < D; i += 256) rr[i] = rel[r * D + i];
        __syncthreads();
        float dot = 0.f;
        if (t < D) {
            #pragma unroll 4
            for (int j = 0; j < D; j++) dot += rr[j] * W[j * D + t];
        }
        red[t] = (t < D) ? dot : -INFINITY;
        __syncthreads();
        for (int ofs = 128; ofs > 0; ofs >>= 1) {
            if (t < ofs) red[t] = fmaxf(red[t], red[t + ofs]);
            __syncthreads();
        }
        float mx = red[0];
        __syncthreads();
        float e = (t < D) ? expf(dot - mx) : 0.f;
        red[t] = e;
        __syncthreads();
        for (int ofs = 128; ofs > 0; ofs >>= 1) {
            if (t < ofs) red[t] += red[t + ofs];
            __syncthreads();
        }
        float inv = (1.f / 3.f) / red[0];
        if (t < D) g_Mtab[(s * R + r) * D + t] = e * inv;
    } else if (b < 2 * R + D) {
        // W_eff[j,o] = sum_k loop_rel[(j+k)%D] * loop_w[k,o], /3, quad layout
        __shared__ float lr[D];
        int j = b - 2 * R;
        for (int i = t; i < D; i += 256) lr[i] = loop_rel[i];
        __syncthreads();
        if (t < D) {
            float a = 0.f;
            int jj = j;
            #pragma unroll 4
            for (int k = 0; k < D; k++) {
                a += lr[jj] * loop_w[k * D + t];
                jj++; if (jj == D) jj = 0;
            }
            g_Weff4[((j >> 2) * D + t) * 4 + (j & 3)] = a * (1.f / 3.f);
        }
    } else {
        // zero counters + stats
        int zb = b - (2 * R + D);
        int base = zb * 1024 + t * 4;
        #pragma unroll
        for (int i = 0; i < 4; i++) {
            int v = base + i;
            if (v < V) g_cnt[v] = 0;
        }
        if (zb == 0 && t < D) { g_stats[t] = 0.f; g_stats[D + t] = 0.f; }
    }
}

// ---------------- CSR build: histogram -> scan -> scatter -------------------
__global__ void k_hist(const int* __restrict__ dst) {
    int i = blockIdx.x * blockDim.x + threadIdx.x;
    if (i < E) atomicAdd(&g_cnt[dst[i]], 1);
}

__global__ void k_scan1() {
    __shared__ int sh[256];
    int b = blockIdx.x, t = threadIdx.x;
    int base = b * 1024 + t * 4;
    int s = 0;
    #pragma unroll
    for (int i = 0; i < 4; i++) {
        int v = base + i;
        if (v < V) s += g_cnt[v];
    }
    sh[t] = s;
    __syncthreads();
    for (int ofs = 128; ofs > 0; ofs >>= 1) {
        if (t < ofs) sh[t] += sh[t + ofs];
        __syncthreads();
    }
    if (t == 0) g_bsum[b] = sh[0];
}

// merged: per-block exclusive prefix over g_bsum + intra-block scan + offsets
__global__ void k_scan3m() {
    __shared__ int sh[256];
    __shared__ int bs[128];
    __shared__ int bpre;
    int b = blockIdx.x, t = threadIdx.x;
    if (t < NBLK) bs[t] = g_bsum[t];
    __syncthreads();
    if (t == 0) {
        int run = 0;
        for (int i = 0; i < b; i++) run += bs[i];
        bpre = run;
        if (b == NBLK - 1) g_off[V] = E;
    }
    int base = b * 1024 + t * 4;
    int c[4];
    int local = 0;
    #pragma unroll
    for (int i = 0; i < 4; i++) {
        int v = base + i;
        c[i] = (v < V) ? g_cnt[v] : 0;
        local += c[i];
    }
    sh[t] = local;
    __syncthreads();
    for (int ofs = 1; ofs < 256; ofs <<= 1) {
        int val = 0;
        if (t >= ofs) val = sh[t - ofs];
        __syncthreads();
        sh[t] += val;
        __syncthreads();
    }
    int excl = sh[t] - local + bpre;
    #pragma unroll
    for (int i = 0; i < 4; i++) {
        int v = base + i;
        if (v < V) { g_off[v] = excl; g_cur[v] = excl; }
        excl += c[i];
    }
}

__global__ void k_scatter(const int* __restrict__ dst,
                          const int* __restrict__ et,
                          const float* __restrict__ norm) {
    int i = blockIdx.x * blockDim.x + threadIdx.x;
    if (i < E) {
        int v = dst[i];
        int p = atomicAdd(&g_cur[v], 1);
        uint2 rec;
        rec.x = (unsigned)et[i] + ((i >= HALF) ? R : 0);
        rec.y = __float_as_uint(norm[i]);
        g_edge[p] = rec;
    }
}

// ---------------- fused main: gather-agg + x@Weff + stats -------------------
__global__ void __launch_bounds__(TPB) k_main(const float* __restrict__ x,
                                              const float* __restrict__ bias,
                                              float* __restrict__ out) {
    __shared__ float xs[NPB * XST];   // row-major x tile, conflict-free fill
    int o  = threadIdx.x;
    int v0 = blockIdx.x * NPB;

    for (int i = o; i < NPB * D; i += TPB) {
        int n = i / D, j = i % D;
        xs[n * XST + j] = x[(v0 + n) * D + j];
    }
    __syncthreads();

    if (o < D) {
        // ---- edge aggregation (Mtab hot in L2), MLP-4 unrolled ----
        float ea[NPB];
        #pragma unroll 1
        for (int n = 0; n < NPB; n++) {
            int e  = g_off[v0 + n];
            int t2 = g_off[v0 + n + 1];
            float a = 0.f;
            for (; e + 4 <= t2; e += 4) {
                uint2 r0 = g_edge[e],     r1 = g_edge[e + 1];
                uint2 r2 = g_edge[e + 2], r3 = g_edge[e + 3];
                float m0 = g_Mtab[(int)r0.x * D + o];
                float m1 = g_Mtab[(int)r1.x * D + o];
                float m2 = g_Mtab[(int)r2.x * D + o];
                float m3 = g_Mtab[(int)r3.x * D + o];
                a += __uint_as_float(r0.y) * m0 + __uint_as_float(r1.y) * m1;
                a += __uint_as_float(r2.y) * m2 + __uint_as_float(r3.y) * m3;
            }
            for (; e < t2; e++) {
                uint2 r = g_edge[e];
                a += __uint_as_float(r.y) * g_Mtab[(int)r.x * D + o];
            }
            ea[n] = a;
        }

        // ---- seed packed accumulators: lo = edge agg, hi = 0 ----
        unsigned long long acc2[NPB];
        #pragma unroll
        for (int n = 0; n < NPB; n++) {
            asm("mov.b64 %0, {%1, %2};"
                : "=l"(acc2[n]) : "f"(ea[n]), "f"(0.f));
        }

        // ---- GEMM: acc += x @ Weff, f32x2 over j-pairs ----
        const ulonglong2* Wq = (const ulonglong2*)g_Weff4;
        #pragma unroll 1
        for (int q = 0; q < NQ; q++) {
            ulonglong2 w = Wq[q * D + o];   // Weff[4q..4q+3][o], LDG.128
            const float* xb = &xs[4 * q];
            #pragma unroll
            for (int n = 0; n < NPB; n++) {
                ulonglong2 xv = *(const ulonglong2*)(xb + n * XST); // LDS.128 bcast
                fma2(acc2[n], xv.x, w.x);
                fma2(acc2[n], xv.y, w.y);
            }
        }

        // ---- epilogue: horizontal add, bias, store, stats ----
        float b = bias[o];
        float lsum = 0.f, lsq = 0.f;
        #pragma unroll
        for (int n = 0; n < NPB; n++) {
            float a0, a1;
            asm("mov.b64 {%0, %1}, %2;" : "=f"(a0), "=f"(a1) : "l"(acc2[n]));
            float p = a0 + a1 + b;
            out[(v0 + n) * D + o] = p;
            lsum += p;
            lsq  += p * p;
        }
        atomicAdd(&g_stats[o], lsum);
        atomicAdd(&g_stats[D + o], lsq);
    }
}

// ---------------- rel_out = rel_repr @ w_rel --------------------------------
__global__ void k_relout(const float* __restrict__ rel,
                         const float* __restrict__ w_rel,
                         float* __restrict__ out2) {
    __shared__ float rr[D];
    int r = blockIdx.x, t = threadIdx.x;
    for (int i = t; i < D; i += 256) rr[i] = rel[r * D + i];
    __syncthreads();
    if (t < D) {
        float a = 0.f;
        #pragma unroll 4
        for (int j = 0; j < D; j++) a += rr[j] * w_rel[j * D + t];
        out2[r * D + t] = a;
    }
}

// ---------------- BN finalize + normalize -----------------------------------
__global__ void k_bn(const float* __restrict__ bnw, const float* __restrict__ bnb) {
    int o = threadIdx.x;
    if (o < D) {
        float mean = g_stats[o] * (1.f / (float)V);
        float var  = g_stats[D + o] * (1.f / (float)V) - mean * mean;
        float sc   = bnw[o] * rsqrtf(var + 1e-5f);
        g_stats[2 * D + o] = sc;
        g_stats[3 * D + o] = bnb[o] - mean * sc;
    }
}

__global__ void k_norm(float* __restrict__ out) {
    __shared__ float sc[D], sh[D];
    int t = threadIdx.x;
    for (int i = t; i < D; i += blockDim.x) {
        sc[i] = g_stats[2 * D + i];
        sh[i] = g_stats[3 * D + i];
    }
    __syncthreads();
    const int n4 = V * D / 4;
    for (int i = blockIdx.x * blockDim.x + t; i < n4; i += gridDim.x * blockDim.x) {
        float4 v = ((float4*)out)[i];
        int o = (i * 4) % D;
        v.x = v.x * sc[o]     + sh[o];
        v.y = v.y * sc[o + 1] + sh[o + 1];
        v.z = v.z * sc[o + 2] + sh[o + 2];
        v.w = v.w * sc[o + 3] + sh[o + 3];
        ((float4*)out)[i] = v;
    }
}

// ---------------- launch ----------------------------------------------------
extern "C" void kernel_launch(void* const* d_in, const int* in_sizes, int n_in,
                              void* d_out, int out_size) {
    const float* x        = (const float*)d_in[0];
    const float* rel      = (const float*)d_in[1];
    const float* enorm    = (const float*)d_in[2];
    const float* in_w     = (const float*)d_in[3];
    const float* out_w    = (const float*)d_in[4];
    const float* loop_w   = (const float*)d_in[5];
    const float* w_rel    = (const float*)d_in[6];
    const float* loop_rel = (const float*)d_in[7];
    const float* bias     = (const float*)d_in[8];
    const float* bnw      = (const float*)d_in[9];
    const float* bnb      = (const float*)d_in[10];
    const int*   et       = (const int*)d_in[11];
    const int*   dst      = (const int*)d_in[12];
    float*       out      = (float*)d_out;

    k_pre<<<2 * R + D + NBLK, 256>>>(rel, in_w, out_w, loop_rel, loop_w);  // 0
    k_hist<<<(E + 255) / 256, 256>>>(dst);                                  // 1
    k_scan1<<<NBLK, 256>>>();                                               // 2
    k_scan3m<<<NBLK, 256>>>();                                              // 3
    k_scatter<<<(E + 255) / 256, 256>>>(dst, et, enorm);                    // 4
    k_main<<<V / NPB, TPB>>>(x, bias, out);                                 // 5 <- ncu -s 5
    k_relout<<<R, 256>>>(rel, w_rel, out + (size_t)V * D);                  // 6
    k_bn<<<1, 256>>>(bnw, bnb);                                             // 7
    k_norm<<<2048, 256>>>(out);                                             // 8
}

// round 4
// speedup vs baseline: 1.0641x; 1.0641x over previous
#include <cuda_runtime.h>
#include <math.h>

#define V      100000
#define E      1000000
#define D      200
#define R      474
#define HALF   500000
#define NPB    16        // nodes per block in main kernel
#define PAD    20        // transposed xs row stride (floats); 80B = 16B-aligned
#define TPB    224       // 7 warps, threads 0..199 own features
#define NBLK   98        // ceil(V/1024) for scan

// ---------------- device scratch (no runtime allocation allowed) ------------
__device__ float    g_Mtab[2 * R * D];        // softmax(rel @ W)/3
__device__ float    g_WeffP[100 * D * 4];     // jp-major, duplicated pairs:
                                              // [(jp*200+o)*4] = {w2jp,w2jp,w2jp+1,w2jp+1}
__device__ int      g_cnt[V];
__device__ int      g_off[V + 1];
__device__ int      g_cur[V];
__device__ uint2    g_edge[E];                // {key, float_bits(norm)}
__device__ int      g_bsum[128];
__device__ float    g_stats[2 * D];           // colsum, colsumsq

__device__ __forceinline__ void fma2(unsigned long long& acc,
                                     unsigned long long a,
                                     unsigned long long b) {
    asm("fma.rn.f32x2 %0, %1, %2, %0;" : "+l"(acc) : "l"(a), "l"(b));
}

// ---------------- merged precompute: mtab + weff + zero + relout -------------
// blocks [0,948): message table; [948,1148): Weff; [1148,1246): zero;
// [1246,1720): rel_out
__global__ void k_pre(const float* __restrict__ rel,
                      const float* __restrict__ in_w,
                      const float* __restrict__ out_w,
                      const float* __restrict__ loop_rel,
                      const float* __restrict__ loop_w,
                      const float* __restrict__ w_rel,
                      float* __restrict__ out2) {
    int b = blockIdx.x, t = threadIdx.x;
    if (b < 2 * R) {
        // softmax(rel_repr[r] @ W) / 3
        __shared__ float rr[D];
        __shared__ float red[256];
        int s = b / R, r = b % R;
        const float* W = s ? out_w : in_w;
        for (int i = t; i < D; i += 256) rr[i] = rel[r * D + i];
        __syncthreads();
        float dot = 0.f;
        if (t < D) {
            #pragma unroll 4
            for (int j = 0; j < D; j++) dot += rr[j] * W[j * D + t];
        }
        red[t] = (t < D) ? dot : -INFINITY;
        __syncthreads();
        for (int ofs = 128; ofs > 0; ofs >>= 1) {
            if (t < ofs) red[t] = fmaxf(red[t], red[t + ofs]);
            __syncthreads();
        }
        float mx = red[0];
        __syncthreads();
        float e = (t < D) ? expf(dot - mx) : 0.f;
        red[t] = e;
        __syncthreads();
        for (int ofs = 128; ofs > 0; ofs >>= 1) {
            if (t < ofs) red[t] += red[t + ofs];
            __syncthreads();
        }
        float inv = (1.f / 3.f) / red[0];
        if (t < D) g_Mtab[(s * R + r) * D + t] = e * inv;
    } else if (b < 2 * R + D) {
        // W_eff[j,o] = sum_k loop_rel[(j+k)%D] * loop_w[k,o], /3, duplicated-pair layout
        __shared__ float lr[D];
        int j = b - 2 * R;
        for (int i = t; i < D; i += 256) lr[i] = loop_rel[i];
        __syncthreads();
        if (t < D) {
            float a = 0.f;
            int jj = j;
            #pragma unroll 4
            for (int k = 0; k < D; k++) {
                a += lr[jj] * loop_w[k * D + t];
                jj++; if (jj == D) jj = 0;
            }
            a *= (1.f / 3.f);
            int base = ((j >> 1) * D + t) * 4 + (j & 1) * 2;
            g_WeffP[base]     = a;
            g_WeffP[base + 1] = a;
        }
    } else if (b < 2 * R + D + NBLK) {
        // zero counters + stats (BOTH halves — t only spans 0..255, 2*D=400!)
        int zb = b - (2 * R + D);
        int base = zb * 1024 + t * 4;
        #pragma unroll
        for (int i = 0; i < 4; i++) {
            int v = base + i;
            if (v < V) g_cnt[v] = 0;
        }
        if (zb == 0 && t < D) { g_stats[t] = 0.f; g_stats[D + t] = 0.f; }
    } else {
        // rel_out = rel_repr @ w_rel
        __shared__ float rr[D];
        int r = b - (2 * R + D + NBLK);
        for (int i = t; i < D; i += 256) rr[i] = rel[r * D + i];
        __syncthreads();
        if (t < D) {
            float a = 0.f;
            #pragma unroll 4
            for (int j = 0; j < D; j++) a += rr[j] * w_rel[j * D + t];
            out2[r * D + t] = a;
        }
    }
}

// ---------------- CSR build: histogram -> scan -> scatter -------------------
__global__ void k_hist(const int* __restrict__ dst) {
    int i = blockIdx.x * blockDim.x + threadIdx.x;
    if (i < E) atomicAdd(&g_cnt[dst[i]], 1);
}

__global__ void k_scan1() {
    __shared__ int sh[256];
    int b = blockIdx.x, t = threadIdx.x;
    int base = b * 1024 + t * 4;
    int s = 0;
    #pragma unroll
    for (int i = 0; i < 4; i++) {
        int v = base + i;
        if (v < V) s += g_cnt[v];
    }
    sh[t] = s;
    __syncthreads();
    for (int ofs = 128; ofs > 0; ofs >>= 1) {
        if (t < ofs) sh[t] += sh[t + ofs];
        __syncthreads();
    }
    if (t == 0) g_bsum[b] = sh[0];
}

// merged: block-prefix over g_bsum + intra-block scan + offsets
__global__ void k_scan3m() {
    __shared__ int sh[256];
    __shared__ int bs[128];
    __shared__ int bpre;
    int b = blockIdx.x, t = threadIdx.x;
    if (t < NBLK) bs[t] = g_bsum[t];
    __syncthreads();
    if (t == 0) {
        int run = 0;
        for (int i = 0; i < b; i++) run += bs[i];
        bpre = run;
        if (b == NBLK - 1) g_off[V] = E;
    }
    int base = b * 1024 + t * 4;
    int c[4];
    int local = 0;
    #pragma unroll
    for (int i = 0; i < 4; i++) {
        int v = base + i;
        c[i] = (v < V) ? g_cnt[v] : 0;
        local += c[i];
    }
    sh[t] = local;
    __syncthreads();
    for (int ofs = 1; ofs < 256; ofs <<= 1) {
        int val = 0;
        if (t >= ofs) val = sh[t - ofs];
        __syncthreads();
        sh[t] += val;
        __syncthreads();
    }
    int excl = sh[t] - local + bpre;
    #pragma unroll
    for (int i = 0; i < 4; i++) {
        int v = base + i;
        if (v < V) { g_off[v] = excl; g_cur[v] = excl; }
        excl += c[i];
    }
}

__global__ void k_scatter(const int* __restrict__ dst,
                          const int* __restrict__ et,
                          const float* __restrict__ norm) {
    int i = blockIdx.x * blockDim.x + threadIdx.x;
    if (i < E) {
        int v = dst[i];
        int p = atomicAdd(&g_cur[v], 1);
        uint2 rec;
        rec.x = (unsigned)et[i] + ((i >= HALF) ? R : 0);
        rec.y = __float_as_uint(norm[i]);
        g_edge[p] = rec;
    }
}

// ---------------- fused main: gather-agg + x@Weff + stats -------------------
__global__ void __launch_bounds__(TPB) k_main(const float* __restrict__ x,
                                              const float* __restrict__ bias,
                                              float* __restrict__ out) {
    __shared__ float xs[D * PAD];   // transposed: xs[j*PAD + n]
    int o  = threadIdx.x;
    int v0 = blockIdx.x * NPB;

    // coalesced GMEM read; 4-way STS conflict (cheap: 100 warp-STS per block)
    for (int i = o; i < NPB * D; i += TPB) {
        int n = i / D, j = i % D;
        xs[j * PAD + n] = x[(v0 + n) * D + j];
    }
    __syncthreads();

    if (o < D) {
        // ---- edge aggregation (Mtab hot in L2), MLP-4 unrolled ----
        float ea[NPB];
        #pragma unroll 1
        for (int n = 0; n < NPB; n++) {
            int e  = g_off[v0 + n];
            int t2 = g_off[v0 + n + 1];
            float a = 0.f;
            for (; e + 4 <= t2; e += 4) {
                uint2 r0 = g_edge[e],     r1 = g_edge[e + 1];
                uint2 r2 = g_edge[e + 2], r3 = g_edge[e + 3];
                float m0 = g_Mtab[(int)r0.x * D + o];
                float m1 = g_Mtab[(int)r1.x * D + o];
                float m2 = g_Mtab[(int)r2.x * D + o];
                float m3 = g_Mtab[(int)r3.x * D + o];
                a += __uint_as_float(r0.y) * m0 + __uint_as_float(r1.y) * m1;
                a += __uint_as_float(r2.y) * m2 + __uint_as_float(r3.y) * m3;
            }
            for (; e < t2; e++) {
                uint2 r = g_edge[e];
                a += __uint_as_float(r.y) * g_Mtab[(int)r.x * D + o];
            }
            ea[n] = a;
        }

        // ---- seed node-pair packed accumulators ----
        unsigned long long acc2[NPB / 2];
        #pragma unroll
        for (int k = 0; k < NPB / 2; k++) {
            asm("mov.b64 %0, {%1, %2};"
                : "=l"(acc2[k]) : "f"(ea[2 * k]), "f"(ea[2 * k + 1]));
        }

        // ---- GEMM: acc += x @ Weff; per jp: 1 LDG.128 + 8 LDS.128 + 16 FMA2 ----
        const ulonglong2* Wp = (const ulonglong2*)g_WeffP;
        #pragma unroll 1
        for (int jp = 0; jp < D / 2; jp++) {
            ulonglong2 w = Wp[jp * D + o];  // {dup w_{2jp}, dup w_{2jp+1}}
            const longlong2* xr0 = (const longlong2*)&xs[(2 * jp) * PAD];
            const longlong2* xr1 = (const longlong2*)&xs[(2 * jp + 1) * PAD];
            #pragma unroll
            for (int m = 0; m < NPB / 4; m++) {
                longlong2 a = xr0[m];   // nodes 4m..4m+3 at j = 2jp (LDS.128 bcast)
                fma2(acc2[2 * m],     (unsigned long long)a.x, w.x);
                fma2(acc2[2 * m + 1], (unsigned long long)a.y, w.x);
                longlong2 bq = xr1[m]; // nodes 4m..4m+3 at j = 2jp+1
                fma2(acc2[2 * m],     (unsigned long long)bq.x, w.y);
                fma2(acc2[2 * m + 1], (unsigned long long)bq.y, w.y);
            }
        }

        // ---- epilogue: unpack, bias, store, stats ----
        float b = bias[o];
        float lsum = 0.f, lsq = 0.f;
        #pragma unroll
        for (int k = 0; k < NPB / 2; k++) {
            float a0, a1;
            asm("mov.b64 {%0, %1}, %2;" : "=f"(a0), "=f"(a1) : "l"(acc2[k]));
            float p0 = a0 + b;
            float p1 = a1 + b;
            out[(v0 + 2 * k) * D + o]     = p0;
            out[(v0 + 2 * k + 1) * D + o] = p1;
            lsum += p0 + p1;
            lsq  += p0 * p0 + p1 * p1;
        }
        atomicAdd(&g_stats[o], lsum);
        atomicAdd(&g_stats[D + o], lsq);
    }
}

// ---------------- BN finalize (per-block) + normalize ------------------------
__global__ void k_norm(const float* __restrict__ bnw,
                       const float* __restrict__ bnb,
                       float* __restrict__ out) {
    __shared__ float sc[D], sh[D];
    int t = threadIdx.x;
    for (int i = t; i < D; i += blockDim.x) {
        float mean = g_stats[i] * (1.f / (float)V);
        float var  = g_stats[D + i] * (1.f / (float)V) - mean * mean;
        float s    = bnw[i] * rsqrtf(var + 1e-5f);
        sc[i] = s;
        sh[i] = bnb[i] - mean * s;
    }
    __syncthreads();
    const int n4 = V * D / 4;
    for (int i = blockIdx.x * blockDim.x + t; i < n4; i += gridDim.x * blockDim.x) {
        float4 v = ((float4*)out)[i];
        int o = (i * 4) % D;
        v.x = v.x * sc[o]     + sh[o];
        v.y = v.y * sc[o + 1] + sh[o + 1];
        v.z = v.z * sc[o + 2] + sh[o + 2];
        v.w = v.w * sc[o + 3] + sh[o + 3];
        ((float4*)out)[i] = v;
    }
}

// ---------------- launch ----------------------------------------------------
extern "C" void kernel_launch(void* const* d_in, const int* in_sizes, int n_in,
                              void* d_out, int out_size) {
    const float* x        = (const float*)d_in[0];
    const float* rel      = (const float*)d_in[1];
    const float* enorm    = (const float*)d_in[2];
    const float* in_w     = (const float*)d_in[3];
    const float* out_w    = (const float*)d_in[4];
    const float* loop_w   = (const float*)d_in[5];
    const float* w_rel    = (const float*)d_in[6];
    const float* loop_rel = (const float*)d_in[7];
    const float* bias     = (const float*)d_in[8];
    const float* bnw      = (const float*)d_in[9];
    const float* bnb      = (const float*)d_in[10];
    const int*   et       = (const int*)d_in[11];
    const int*   dst      = (const int*)d_in[12];
    float*       out      = (float*)d_out;

    k_pre<<<2 * R + D + NBLK + R, 256>>>(rel, in_w, out_w, loop_rel, loop_w,
                                         w_rel, out + (size_t)V * D);   // 0
    k_hist<<<(E + 255) / 256, 256>>>(dst);                              // 1
    k_scan1<<<NBLK, 256>>>();                                           // 2
    k_scan3m<<<NBLK, 256>>>();                                          // 3
    k_scatter<<<(E + 255) / 256, 256>>>(dst, et, enorm);                // 4
    k_main<<<V / NPB, TPB>>>(x, bias, out);                             // 5
    k_norm<<<2048, 256>>>(bnw, bnb, out);                               // 6
}

// round 5
// speedup vs baseline: 1.2183x; 1.1449x over previous
#include <cuda_runtime.h>
#include <math.h>

#define V      100000
#define E      1000000
#define D      200
#define R      474
#define HALF   500000
#define NPB    16        // nodes per block in main kernel
#define NPG    8         // nodes per thread-group
#define PAD    20        // transposed xs row stride (floats); 80B rows, 16B aligned
#define TPB    448       // 2 groups x 224 threads; o = t%224, active o<200
#define NBLK   98        // ceil(V/1024) for scan

// ---------------- device scratch (no runtime allocation allowed) ------------
__device__ float    g_Mtab[2 * R * D];        // softmax(rel @ W)/3
__device__ float    g_Weff[D * D];            // 160KB, fits L1 -> keep plain!
__device__ int      g_cnt[V];
__device__ int      g_off[V + 1];
__device__ int      g_cur[V];
__device__ uint2    g_edge[E];                // {key, float_bits(norm)}
__device__ int      g_bsum[128];
__device__ float    g_stats[2 * D];           // colsum, colsumsq

__device__ __forceinline__ void fma2(unsigned long long& acc,
                                     unsigned long long a,
                                     unsigned long long b) {
    asm("fma.rn.f32x2 %0, %1, %2, %0;" : "+l"(acc) : "l"(a), "l"(b));
}

// ---------------- merged precompute: mtab + weff + zero + relout -------------
__global__ void k_pre(const float* __restrict__ rel,
                      const float* __restrict__ in_w,
                      const float* __restrict__ out_w,
                      const float* __restrict__ loop_rel,
                      const float* __restrict__ loop_w,
                      const float* __restrict__ w_rel,
                      float* __restrict__ out2) {
    int b = blockIdx.x, t = threadIdx.x;
    if (b < 2 * R) {
        // softmax(rel_repr[r] @ W) / 3
        __shared__ float rr[D];
        __shared__ float red[256];
        int s = b / R, r = b % R;
        const float* W = s ? out_w : in_w;
        for (int i = t; i < D; i += 256) rr[i] = rel[r * D + i];
        __syncthreads();
        float dot = 0.f;
        if (t < D) {
            #pragma unroll 4
            for (int j = 0; j < D; j++) dot += rr[j] * W[j * D + t];
        }
        red[t] = (t < D) ? dot : -INFINITY;
        __syncthreads();
        for (int ofs = 128; ofs > 0; ofs >>= 1) {
            if (t < ofs) red[t] = fmaxf(red[t], red[t + ofs]);
            __syncthreads();
        }
        float mx = red[0];
        __syncthreads();
        float e = (t < D) ? expf(dot - mx) : 0.f;
        red[t] = e;
        __syncthreads();
        for (int ofs = 128; ofs > 0; ofs >>= 1) {
            if (t < ofs) red[t] += red[t + ofs];
            __syncthreads();
        }
        float inv = (1.f / 3.f) / red[0];
        if (t < D) g_Mtab[(s * R + r) * D + t] = e * inv;
    } else if (b < 2 * R + D) {
        // W_eff[j,o] = sum_k loop_rel[(j+k)%D] * loop_w[k,o], /3  (plain layout)
        __shared__ float lr[D];
        int j = b - 2 * R;
        for (int i = t; i < D; i += 256) lr[i] = loop_rel[i];
        __syncthreads();
        if (t < D) {
            float a = 0.f;
            int jj = j;
            #pragma unroll 4
            for (int k = 0; k < D; k++) {
                a += lr[jj] * loop_w[k * D + t];
                jj++; if (jj == D) jj = 0;
            }
            g_Weff[j * D + t] = a * (1.f / 3.f);
        }
    } else if (b < 2 * R + D + NBLK) {
        // zero counters + stats (both halves; t spans 0..255 only)
        int zb = b - (2 * R + D);
        int base = zb * 1024 + t * 4;
        #pragma unroll
        for (int i = 0; i < 4; i++) {
            int v = base + i;
            if (v < V) g_cnt[v] = 0;
        }
        if (zb == 0 && t < D) { g_stats[t] = 0.f; g_stats[D + t] = 0.f; }
    } else {
        // rel_out = rel_repr @ w_rel
        __shared__ float rr[D];
        int r = b - (2 * R + D + NBLK);
        for (int i = t; i < D; i += 256) rr[i] = rel[r * D + i];
        __syncthreads();
        if (t < D) {
            float a = 0.f;
            #pragma unroll 4
            for (int j = 0; j < D; j++) a += rr[j] * w_rel[j * D + t];
            out2[r * D + t] = a;
        }
    }
}

// ---------------- CSR build: histogram -> scan -> scatter -------------------
__global__ void k_hist(const int* __restrict__ dst) {
    int i = blockIdx.x * blockDim.x + threadIdx.x;
    if (i < E) atomicAdd(&g_cnt[dst[i]], 1);
}

__global__ void k_scan1() {
    __shared__ int sh[256];
    int b = blockIdx.x, t = threadIdx.x;
    int base = b * 1024 + t * 4;
    int s = 0;
    #pragma unroll
    for (int i = 0; i < 4; i++) {
        int v = base + i;
        if (v < V) s += g_cnt[v];
    }
    sh[t] = s;
    __syncthreads();
    for (int ofs = 128; ofs > 0; ofs >>= 1) {
        if (t < ofs) sh[t] += sh[t + ofs];
        __syncthreads();
    }
    if (t == 0) g_bsum[b] = sh[0];
}

__global__ void k_scan3m() {
    __shared__ int sh[256];
    __shared__ int bs[128];
    __shared__ int bpre;
    int b = blockIdx.x, t = threadIdx.x;
    if (t < NBLK) bs[t] = g_bsum[t];
    __syncthreads();
    if (t == 0) {
        int run = 0;
        for (int i = 0; i < b; i++) run += bs[i];
        bpre = run;
        if (b == NBLK - 1) g_off[V] = E;
    }
    int base = b * 1024 + t * 4;
    int c[4];
    int local = 0;
    #pragma unroll
    for (int i = 0; i < 4; i++) {
        int v = base + i;
        c[i] = (v < V) ? g_cnt[v] : 0;
        local += c[i];
    }
    sh[t] = local;
    __syncthreads();
    for (int ofs = 1; ofs < 256; ofs <<= 1) {
        int val = 0;
        if (t >= ofs) val = sh[t - ofs];
        __syncthreads();
        sh[t] += val;
        __syncthreads();
    }
    int excl = sh[t] - local + bpre;
    #pragma unroll
    for (int i = 0; i < 4; i++) {
        int v = base + i;
        if (v < V) { g_off[v] = excl; g_cur[v] = excl; }
        excl += c[i];
    }
}

__global__ void k_scatter(const int* __restrict__ dst,
                          const int* __restrict__ et,
                          const float* __restrict__ norm) {
    int i = blockIdx.x * blockDim.x + threadIdx.x;
    if (i < E) {
        int v = dst[i];
        int p = atomicAdd(&g_cur[v], 1);
        uint2 rec;
        rec.x = (unsigned)et[i] + ((i >= HALF) ? R : 0);
        rec.y = __float_as_uint(norm[i]);
        g_edge[p] = rec;
    }
}

// ---------------- fused main: gather-agg + x@Weff + stats -------------------
// 2 thread-groups per block: group g handles nodes [8g, 8g+8) of the 16-node tile.
__global__ void __launch_bounds__(TPB) k_main(const float* __restrict__ x,
                                              const float* __restrict__ bias,
                                              float* __restrict__ out) {
    __shared__ float xs[D * PAD];   // transposed: xs[j*PAD + n]
    int t  = threadIdx.x;
    int g  = t / 224;               // group 0 or 1
    int o  = t % 224;               // feature id, active if < 200
    int v0 = blockIdx.x * NPB;
    int nb = g * NPG;               // node base within tile

    // coalesced fill (all 448 threads)
    for (int i = t; i < NPB * D; i += TPB) {
        int n = i / D, j = i % D;
        xs[j * PAD + n] = x[(v0 + n) * D + j];
    }
    __syncthreads();

    if (o < D) {
        // ---- edge aggregation for this group's 8 nodes (MLP-4 unrolled) ----
        float ea[NPG];
        #pragma unroll 1
        for (int n = 0; n < NPG; n++) {
            int vtx = v0 + nb + n;
            int e  = g_off[vtx];
            int t2 = g_off[vtx + 1];
            float a = 0.f;
            for (; e + 4 <= t2; e += 4) {
                uint2 r0 = g_edge[e],     r1 = g_edge[e + 1];
                uint2 r2 = g_edge[e + 2], r3 = g_edge[e + 3];
                float m0 = g_Mtab[(int)r0.x * D + o];
                float m1 = g_Mtab[(int)r1.x * D + o];
                float m2 = g_Mtab[(int)r2.x * D + o];
                float m3 = g_Mtab[(int)r3.x * D + o];
                a += __uint_as_float(r0.y) * m0 + __uint_as_float(r1.y) * m1;
                a += __uint_as_float(r2.y) * m2 + __uint_as_float(r3.y) * m3;
            }
            for (; e < t2; e++) {
                uint2 r = g_edge[e];
                a += __uint_as_float(r.y) * g_Mtab[(int)r.x * D + o];
            }
            ea[n] = a;
        }

        // ---- seed node-pair packed accumulators (4 x 64-bit) ----
        unsigned long long acc2[NPG / 2];
        #pragma unroll
        for (int k = 0; k < NPG / 2; k++) {
            asm("mov.b64 %0, {%1, %2};"
                : "=l"(acc2[k]) : "f"(ea[2 * k]), "f"(ea[2 * k + 1]));
        }

        // ---- GEMM: acc += x @ Weff
        // per j: 1 scalar LDG (L1-resident 160KB table) + 1 mov + 2 LDS.128 + 4 FMA2
        #pragma unroll 2
        for (int jp = 0; jp < D / 2; jp++) {
            int j0 = 2 * jp;
            float w0 = g_Weff[j0 * D + o];
            float w1 = g_Weff[(j0 + 1) * D + o];
            unsigned long long wd0, wd1;
            asm("mov.b64 %0, {%1, %1};" : "=l"(wd0) : "f"(w0));
            asm("mov.b64 %0, {%1, %1};" : "=l"(wd1) : "f"(w1));
            const longlong2* xr0 = (const longlong2*)&xs[j0 * PAD + nb];
            const longlong2* xr1 = (const longlong2*)&xs[(j0 + 1) * PAD + nb];
            longlong2 a = *xr0;       // nodes nb..nb+3 at j0 (LDS.128 bcast)
            fma2(acc2[0], (unsigned long long)a.x, wd0);
            fma2(acc2[1], (unsigned long long)a.y, wd0);
            longlong2 b2 = xr0[1];    // nodes nb+4..nb+7 at j0
            fma2(acc2[2], (unsigned long long)b2.x, wd0);
            fma2(acc2[3], (unsigned long long)b2.y, wd0);
            longlong2 c = *xr1;       // nodes nb..nb+3 at j0+1
            fma2(acc2[0], (unsigned long long)c.x, wd1);
            fma2(acc2[1], (unsigned long long)c.y, wd1);
            longlong2 d = xr1[1];     // nodes nb+4..nb+7 at j0+1
            fma2(acc2[2], (unsigned long long)d.x, wd1);
            fma2(acc2[3], (unsigned long long)d.y, wd1);
        }

        // ---- epilogue: unpack, bias, store, stats ----
        float b = bias[o];
        float lsum = 0.f, lsq = 0.f;
        #pragma unroll
        for (int k = 0; k < NPG / 2; k++) {
            float a0, a1;
            asm("mov.b64 {%0, %1}, %2;" : "=f"(a0), "=f"(a1) : "l"(acc2[k]));
            float p0 = a0 + b;
            float p1 = a1 + b;
            out[(v0 + nb + 2 * k) * D + o]     = p0;
            out[(v0 + nb + 2 * k + 1) * D + o] = p1;
            lsum += p0 + p1;
            lsq  += p0 * p0 + p1 * p1;
        }
        atomicAdd(&g_stats[o], lsum);
        atomicAdd(&g_stats[D + o], lsq);
    }
}

// ---------------- BN finalize (per-block) + normalize ------------------------
__global__ void k_norm(const float* __restrict__ bnw,
                       const float* __restrict__ bnb,
                       float* __restrict__ out) {
    __shared__ float sc[D], sh[D];
    int t = threadIdx.x;
    for (int i = t; i < D; i += blockDim.x) {
        float mean = g_stats[i] * (1.f / (float)V);
        float var  = g_stats[D + i] * (1.f / (float)V) - mean * mean;
        float s    = bnw[i] * rsqrtf(var + 1e-5f);
        sc[i] = s;
        sh[i] = bnb[i] - mean * s;
    }
    __syncthreads();
    const int n4 = V * D / 4;
    for (int i = blockIdx.x * blockDim.x + t; i < n4; i += gridDim.x * blockDim.x) {
        float4 v = ((float4*)out)[i];
        int o = (i * 4) % D;
        v.x = v.x * sc[o]     + sh[o];
        v.y = v.y * sc[o + 1] + sh[o + 1];
        v.z = v.z * sc[o + 2] + sh[o + 2];
        v.w = v.w * sc[o + 3] + sh[o + 3];
        ((float4*)out)[i] = v;
    }
}

// ---------------- launch ----------------------------------------------------
extern "C" void kernel_launch(void* const* d_in, const int* in_sizes, int n_in,
                              void* d_out, int out_size) {
    const float* x        = (const float*)d_in[0];
    const float* rel      = (const float*)d_in[1];
    const float* enorm    = (const float*)d_in[2];
    const float* in_w     = (const float*)d_in[3];
    const float* out_w    = (const float*)d_in[4];
    const float* loop_w   = (const float*)d_in[5];
    const float* w_rel    = (const float*)d_in[6];
    const float* loop_rel = (const float*)d_in[7];
    const float* bias     = (const float*)d_in[8];
    const float* bnw      = (const float*)d_in[9];
    const float* bnb      = (const float*)d_in[10];
    const int*   et       = (const int*)d_in[11];
    const int*   dst      = (const int*)d_in[12];
    float*       out      = (float*)d_out;

    k_pre<<<2 * R + D + NBLK + R, 256>>>(rel, in_w, out_w, loop_rel, loop_w,
                                         w_rel, out + (size_t)V * D);   // 0
    k_hist<<<(E + 255) / 256, 256>>>(dst);                              // 1
    k_scan1<<<NBLK, 256>>>();                                           // 2
    k_scan3m<<<NBLK, 256>>>();                                          // 3
    k_scatter<<<(E + 255) / 256, 256>>>(dst, et, enorm);                // 4
    k_main<<<V / NPB, TPB>>>(x, bias, out);                             // 5
    k_norm<<<2048, 256>>>(bnw, bnb, out);                               // 6
}